// round 9
// baseline (speedup 1.0000x reference)
#include <cuda_runtime.h>
#include <cuda_bf16.h>

#define N_NODES 50000
#define N_EDGES 800000
#define NHID 128
#define BN_EPS 1e-5f
#define NBLK 196                 // ceil(50000/256)
#define FE_BLOCKS 592            // 4 per SM x 148 — co-residency guaranteed
#define NTILE64 782              // ceil(50000/64)

typedef unsigned long long u64;
typedef unsigned int u32;

// ---------------- helpers ----------------------------------------------------
__device__ __forceinline__ u32 smem_u32(const void* p) {
    u32 a;
    asm("{ .reg .u64 t; cvta.to.shared.u64 t, %1; cvt.u32.u64 %0, t; }"
        : "=r"(a) : "l"(p));
    return a;
}
__device__ __forceinline__ void lds2(u32 addr, u32& a, u32& b) {
    asm volatile("ld.shared.v2.u32 {%0, %1}, [%2];" : "=r"(a), "=r"(b) : "r"(addr));
}
__device__ __forceinline__ void sts2f(u32 addr, float a, float b) {
    asm volatile("st.shared.v2.f32 [%0], {%1, %2};" :: "r"(addr), "f"(a), "f"(b) : "memory");
}
__device__ __forceinline__ void mma16816(float* c, u32 a0, u32 a1, u32 a2, u32 a3,
                                         u32 b0, u32 b1) {
    asm volatile(
        "mma.sync.aligned.m16n8k16.row.col.f32.bf16.bf16.f32 "
        "{%0,%1,%2,%3}, {%4,%5,%6,%7}, {%8,%9}, {%0,%1,%2,%3};"
        : "+f"(c[0]), "+f"(c[1]), "+f"(c[2]), "+f"(c[3])
        : "r"(a0), "r"(a1), "r"(a2), "r"(a3), "r"(b0), "r"(b1));
}
// split float4 -> interleaved uint4 {hi01, lo01, hi23, lo23} (bf16x2 words)
__device__ __forceinline__ uint4 split4i(float4 v) {
    __nv_bfloat162 h0 = __float22bfloat162_rn(make_float2(v.x, v.y));
    __nv_bfloat162 h1 = __float22bfloat162_rn(make_float2(v.z, v.w));
    float2 r0 = make_float2(v.x - __bfloat162float(h0.x), v.y - __bfloat162float(h0.y));
    float2 r1 = make_float2(v.z - __bfloat162float(h1.x), v.w - __bfloat162float(h1.y));
    __nv_bfloat162 l0 = __float22bfloat162_rn(r0);
    __nv_bfloat162 l1 = __float22bfloat162_rn(r1);
    uint4 q;
    q.x = *(u32*)&h0; q.y = *(u32*)&l0;
    q.z = *(u32*)&h1; q.w = *(u32*)&l1;
    return q;
}

// ---------------- scratch ----------------------------------------------------
__device__ float g_sum[NHID];
__device__ float g_sumsq[NHID];
__device__ float g_c2[NHID];
__device__ int   g_count[N_NODES];
__device__ int   g_off[N_NODES + 1];
__device__ int   g_cursor[N_NODES];
__device__ int   g_srcsorted[N_EDGES];
__device__ int   g_bsum[NBLK];
__device__ int   g_bar_count;                  // zero-init; returns to 0
__device__ volatile unsigned g_bar_gen;
__device__ __align__(16) unsigned char g_Ahl[(size_t)(NTILE64 * 64) * 512];
__device__ __align__(16) unsigned char g_Hhl[(size_t)(NTILE64 * 64) * 512];
__device__ __align__(16) unsigned char g_W1hl[65536];
__device__ __align__(16) unsigned char g_W2hl[65536];

// ---------------- software grid barrier (all blocks resident) -----------------
__device__ __forceinline__ void grid_barrier() {
    __syncthreads();
    if (threadIdx.x == 0) {
        unsigned gen = g_bar_gen;
        __threadfence();
        if (atomicAdd(&g_bar_count, 1) == FE_BLOCKS - 1) {
            g_bar_count = 0;
            __threadfence();
            g_bar_gen = gen + 1;
        } else {
            while (g_bar_gen == gen) __nanosleep(32);
        }
    }
    __syncthreads();
    __threadfence();
}

// ---------------- persistent front-end ----------------------------------------
// P1 hist -> P2 partials -> P3 offsets (+W1 prep) -> P4 reorder -> P5 gather
__global__ __launch_bounds__(256, 4) void frontend_kernel(
    const int* __restrict__ ei, const float* __restrict__ x,
    const float* __restrict__ W1) {
    const int tid = threadIdx.x;
    const int bid = blockIdx.x;
    const int gid = bid * 256 + tid;
    const int n4 = N_EDGES / 4;                  // 200000 int4s per half
    const int4* s4 = (const int4*)ei;
    const int4* d4 = (const int4*)(ei + N_EDGES);

    // ---- P1: histogram of dst ----
    for (int i = gid; i < n4; i += FE_BLOCKS * 256) {
        int4 d = d4[i];
        atomicAdd(&g_count[d.x], 1); atomicAdd(&g_count[d.y], 1);
        atomicAdd(&g_count[d.z], 1); atomicAdd(&g_count[d.w], 1);
    }
    grid_barrier();

    // ---- P2: per-chunk partial sums (blocks 0..NBLK-1) ----
    if (bid < NBLK) {
        int i = bid * 256 + tid;
        int v = (i < N_NODES) ? g_count[i] : 0;
#pragma unroll
        for (int o = 16; o > 0; o >>= 1) v += __shfl_down_sync(~0u, v, o);
        __shared__ int ws[8];
        if ((tid & 31) == 0) ws[tid >> 5] = v;
        __syncthreads();
        if (tid == 0) {
            int s = 0;
#pragma unroll
            for (int k = 0; k < 8; k++) s += ws[k];
            g_bsum[bid] = s;
        }
    }
    grid_barrier();

    // ---- P3: offsets (blocks 0..NBLK-1); W1 bf16 prep (block NBLK) ----
    if (bid < NBLK) {
        __shared__ int sb[256];
        __shared__ int sh[256];
        sb[tid] = (tid < NBLK) ? g_bsum[tid] : 0;
        __syncthreads();
#pragma unroll
        for (int o = 1; o < 256; o <<= 1) {
            int u = (tid >= o) ? sb[tid - o] : 0;
            __syncthreads();
            sb[tid] += u;
            __syncthreads();
        }
        int base = (bid > 0) ? sb[bid - 1] : 0;

        int i = bid * 256 + tid;
        int v = (i < N_NODES) ? g_count[i] : 0;
        sh[tid] = v;
        __syncthreads();
#pragma unroll
        for (int o = 1; o < 256; o <<= 1) {
            int u = (tid >= o) ? sh[tid - o] : 0;
            __syncthreads();
            sh[tid] += u;
            __syncthreads();
        }
        int off = base + sh[tid] - v;
        if (i < N_NODES) {
            g_off[i] = off;
            g_cursor[i] = off;
            g_count[i] = 0;                       // self-clean for replay
        } else if (i == N_NODES) {
            g_off[N_NODES] = N_EDGES;
        }
        if (bid == 0 && tid < NHID) { g_sum[tid] = 0.f; g_sumsq[tid] = 0.f; }
    } else if (bid == NBLK && tid < 128) {
        const float4* wr = (const float4*)(W1 + tid * NHID);
        uint4* dst = (uint4*)g_W1hl + tid * 32;
#pragma unroll 8
        for (int k4 = 0; k4 < 32; k4++) dst[k4] = split4i(wr[k4]);
    }
    grid_barrier();

    // ---- P4: reorder src by dst ----
    for (int i = gid; i < n4; i += FE_BLOCKS * 256) {
        int4 s = s4[i];
        int4 d = d4[i];
        g_srcsorted[atomicAdd(&g_cursor[d.x], 1)] = s.x;
        g_srcsorted[atomicAdd(&g_cursor[d.y], 1)] = s.y;
        g_srcsorted[atomicAdd(&g_cursor[d.z], 1)] = s.z;
        g_srcsorted[atomicAdd(&g_cursor[d.w], 1)] = s.w;
    }
    grid_barrier();

    // ---- P5: pull-aggregate -> interleaved bf16 hi/lo (warp per node) ----
    const int lane = tid & 31;
    const int wglobal = bid * 8 + (tid >> 5);
    for (int node = wglobal; node < N_NODES; node += FE_BLOCKS * 8) {
        int start = g_off[node];
        int deg = g_off[node + 1] - start;
        float4 acc = ((const float4*)(x + (size_t)node * NHID))[lane];
        const int* sl = g_srcsorted + start;
        int j = 0;
        for (; j + 4 <= deg; j += 4) {
            int s0 = sl[j], s1 = sl[j + 1], s2 = sl[j + 2], s3 = sl[j + 3];
            float4 v0 = ((const float4*)(x + (size_t)s0 * NHID))[lane];
            float4 v1 = ((const float4*)(x + (size_t)s1 * NHID))[lane];
            float4 v2 = ((const float4*)(x + (size_t)s2 * NHID))[lane];
            float4 v3 = ((const float4*)(x + (size_t)s3 * NHID))[lane];
            acc.x += v0.x + v1.x + v2.x + v3.x;
            acc.y += v0.y + v1.y + v2.y + v3.y;
            acc.z += v0.z + v1.z + v2.z + v3.z;
            acc.w += v0.w + v1.w + v2.w + v3.w;
        }
        for (; j < deg; j++) {
            int s0 = sl[j];
            float4 v0 = ((const float4*)(x + (size_t)s0 * NHID))[lane];
            acc.x += v0.x; acc.y += v0.y; acc.z += v0.z; acc.w += v0.w;
        }
        ((uint4*)g_Ahl)[(size_t)node * 32 + lane] = split4i(acc);
    }
}

// ---------------- BN fold -> W2 bf16 tiles + c2 --------------------------------
__global__ __launch_bounds__(128) void w2prep_kernel(
    const float* __restrict__ gamma, const float* __restrict__ beta,
    const float* __restrict__ W2, const float* __restrict__ b2) {
    __shared__ float sA[NHID], sB[NHID];
    int t = threadIdx.x;
    float mean = g_sum[t] * (1.f / N_NODES);
    float var = g_sumsq[t] * (1.f / N_NODES) - mean * mean;
    float a = gamma[t] * rsqrtf(var + BN_EPS);
    sA[t] = a;
    sB[t] = beta[t] - mean * a;
    __syncthreads();
    float c = b2[t];
    const float4* wr = (const float4*)(W2 + t * NHID);
    uint4* dst = (uint4*)g_W2hl + t * 32;
#pragma unroll 8
    for (int k4 = 0; k4 < 32; k4++) {
        float4 w = wr[k4];
        int k = k4 * 4;
        c += w.x * sB[k] + w.y * sB[k + 1] + w.z * sB[k + 2] + w.w * sB[k + 3];
        w.x *= sA[k]; w.y *= sA[k + 1]; w.z *= sA[k + 2]; w.w *= sA[k + 3];
        dst[k4] = split4i(w);
    }
    g_c2[t] = c;
}

// ---------------- HMMA GEMM: 64-row tiles, 2 CTA/SM ---------------------------
// 8 warps: wr=wid>>1 -> 16-row strip, wc=wid&1 -> 64-col half.
#define SROW 66                       // u64 per row (64 + 2 pad)
#define A_BYTES (64 * SROW * 8)       // 33792
#define W_BYTES (128 * SROW * 8)      // 67584
#define GSM2 (A_BYTES + W_BYTES + 512)

template <bool FIRST>
__global__ __launch_bounds__(256) void mma_kernel(
    const unsigned char* __restrict__ Ahl, const unsigned char* __restrict__ Whl,
    const float* __restrict__ bias,
    unsigned char* __restrict__ outHhl, float* __restrict__ outF) {
    extern __shared__ unsigned char sm[];
    const u32 smb = smem_u32(sm);
    const u32 aw = smb;
    const u32 bw = smb + A_BYTES;
    float* biasS = (float*)(sm + A_BYTES + W_BYTES);
    float* ht = (float*)sm;           // 64 x 132 fp32 overlay (epilogue)

    const int tid = threadIdx.x;
    const int wid = tid >> 5;
    const int lane = tid & 31;
    const int g = lane >> 2;
    const int tig = lane & 3;
    const int r0 = (wid >> 1) * 16;
    const int nbase = (wid & 1) * 64;
    const int bidx = blockIdx.x;
    const int rows = min(64, N_NODES - bidx * 64);

    // ---- stage tiles: A 2048 uint4, W 4096 uint4 -> [row][33 uint4] ----
    {
        const uint4* gA = (const uint4*)Ahl + (size_t)bidx * 2048;
        const uint4* gW = (const uint4*)Whl;
        uint4* sA4 = (uint4*)sm;
        uint4* sW4 = (uint4*)(sm + A_BYTES);
#pragma unroll
        for (int it = 0; it < 8; it++) {
            int i = it * 256 + tid;
            sA4[(i >> 5) * 33 + (i & 31)] = gA[i];
        }
#pragma unroll
        for (int it = 0; it < 16; it++) {
            int i = it * 256 + tid;
            sW4[(i >> 5) * 33 + (i & 31)] = gW[i];
        }
        if (tid < 128) biasS[tid] = bias[tid];
    }
    __syncthreads();

    // ---- mainloop ----
    float acc[8][4];
#pragma unroll
    for (int nb = 0; nb < 8; nb++)
#pragma unroll
        for (int q = 0; q < 4; q++) acc[nb][q] = 0.f;

    for (int ks = 0; ks < 8; ks++) {
        const int kb2 = ks * 8;
        u32 ah[4], al[4];
        int rb = r0 + g;
        lds2(aw + (rb * SROW + tig + kb2) * 8,       ah[0], al[0]);
        lds2(aw + ((rb + 8) * SROW + tig + kb2) * 8, ah[1], al[1]);
        lds2(aw + (rb * SROW + tig + 4 + kb2) * 8,       ah[2], al[2]);
        lds2(aw + ((rb + 8) * SROW + tig + 4 + kb2) * 8, ah[3], al[3]);
#pragma unroll
        for (int nb = 0; nb < 8; nb++) {
            int nn = nbase + nb * 8 + g;
            u32 b0h, b0l, b1h, b1l;
            lds2(bw + (nn * SROW + tig + kb2) * 8,     b0h, b0l);
            lds2(bw + (nn * SROW + tig + 4 + kb2) * 8, b1h, b1l);
            mma16816(acc[nb], ah[0], ah[1], ah[2], ah[3], b0h, b1h);
            mma16816(acc[nb], ah[0], ah[1], ah[2], ah[3], b0l, b1l);
            mma16816(acc[nb], al[0], al[1], al[2], al[3], b0h, b1h);
        }
    }
    __syncthreads();   // done reading A/W smem; reuse as ht

    // ---- fragments -> ht (bias, relu, row mask) ----
#pragma unroll
    for (int nb = 0; nb < 8; nb++) {
        int row = r0 + g;
        int col = nbase + nb * 8 + 2 * tig;
        float bc0 = biasS[col], bc1 = biasS[col + 1];
        float v0 = acc[nb][0] + bc0, v1 = acc[nb][1] + bc1;
        float v2 = acc[nb][2] + bc0, v3 = acc[nb][3] + bc1;
        if (FIRST) {
            v0 = fmaxf(v0, 0.f); v1 = fmaxf(v1, 0.f);
            v2 = fmaxf(v2, 0.f); v3 = fmaxf(v3, 0.f);
        }
        if (row >= rows) { v0 = 0.f; v1 = 0.f; }
        if (row + 8 >= rows) { v2 = 0.f; v3 = 0.f; }
        sts2f(smb + (row * 132 + col) * 4, v0, v1);
        sts2f(smb + ((row + 8) * 132 + col) * 4, v2, v3);
    }
    __syncthreads();

    // ---- epilogue ----
    if (FIRST) {
        if (tid < 128) {
            float s1 = 0.f, s2 = 0.f;
#pragma unroll 8
            for (int r = 0; r < 64; r++) {
                float v = ht[r * 132 + tid];
                s1 += v;
                s2 += v * v;
            }
            atomicAdd(&g_sum[tid], s1);
            atomicAdd(&g_sumsq[tid], s2);
        }
        uint4* oh = (uint4*)outHhl + (size_t)bidx * 2048;
        for (int i = tid; i < 2048; i += 256) {
            int row = i >> 5, c4 = i & 31;
            float4 v = *(float4*)&ht[row * 132 + c4 * 4];
            oh[row * 32 + c4] = split4i(v);
        }
    } else {
        for (int i = tid; i < 2048; i += 256) {
            int row = i >> 5, c4 = i & 31;
            if (row < rows) {
                float4 v = *(float4*)&ht[row * 132 + c4 * 4];
                ((float4*)(outF + (size_t)(bidx * 64 + row) * NHID))[c4] = v;
            }
        }
    }
}

// ---------------- launch ------------------------------------------------------
extern "C" void kernel_launch(void* const* d_in, const int* in_sizes, int n_in,
                              void* d_out, int out_size) {
    const float* x     = (const float*)d_in[0];
    const int*   ei    = (const int*)d_in[1];
    const float* W1    = (const float*)d_in[2];
    const float* b1    = (const float*)d_in[3];
    const float* gamma = (const float*)d_in[4];
    const float* beta  = (const float*)d_in[5];
    const float* W2    = (const float*)d_in[6];
    const float* b2    = (const float*)d_in[7];
    float* out = (float*)d_out;

    unsigned char *ahl, *hhl, *w1hl, *w2hl;
    float* c2p;
    cudaGetSymbolAddress((void**)&ahl, g_Ahl);
    cudaGetSymbolAddress((void**)&hhl, g_Hhl);
    cudaGetSymbolAddress((void**)&w1hl, g_W1hl);
    cudaGetSymbolAddress((void**)&w2hl, g_W2hl);
    cudaGetSymbolAddress((void**)&c2p, g_c2);

    cudaFuncSetAttribute(mma_kernel<true>,
                         cudaFuncAttributeMaxDynamicSharedMemorySize, GSM2);
    cudaFuncSetAttribute(mma_kernel<false>,
                         cudaFuncAttributeMaxDynamicSharedMemorySize, GSM2);

    frontend_kernel<<<FE_BLOCKS, 256>>>(ei, x, W1);
    mma_kernel<true><<<NTILE64, 256, GSM2>>>(ahl, w1hl, b1, hhl, nullptr);
    w2prep_kernel<<<1, 128>>>(gamma, beta, W2, b2);
    mma_kernel<false><<<NTILE64, 256, GSM2>>>(hhl, w2hl, c2p, nullptr, out);
}